// round 4
// baseline (speedup 1.0000x reference)
#include <cuda_runtime.h>
#include <stdint.h>

// Ragged node-batch -> batch reconstruction, output-centric formulation.
// Inputs: src [L,NB], memory_bank [L,NB,D], lengths [NB], recover [NB]
// Output (flat): src_out [MAX_LEN,B], mb_out [MAX_LEN,B,D], hidden [B,D], lengths_out [B]
// Shapes here: B=32, N=64, L=128, D=256, NB=2048, MAX_LEN=8192.

#define ROWS 32          // output token rows per block
#define NNODES 64        // N (nodes per batch)
#define LANES 64         // D/4 float4 lanes per row

__global__ void zero_hidden_kernel(float* __restrict__ hidden, int n4)
{
    int i = blockIdx.x * blockDim.x + threadIdx.x;
    if (i < n4)
        reinterpret_cast<float4*>(hidden)[i] = make_float4(0.f, 0.f, 0.f, 0.f);
}

// Block = (chunk, b): owns output token rows [chunk*ROWS, (chunk+1)*ROWS) of
// batch b. 256 threads: lane = float4 column, rsub = row subgroup (4).
__global__ void __launch_bounds__(256)
recon_kernel(const float* __restrict__ src,
             const float* __restrict__ mb,
             const int* __restrict__ lengths,
             const int* __restrict__ recover,
             float* __restrict__ src_out,
             float* __restrict__ mb_out,
             float* __restrict__ hidden,
             float* __restrict__ lengths_out,
             int B, int N, int D, int NB, int MAX_LEN)
{
    const int chunk = blockIdx.x;
    const int b     = blockIdx.y;
    const int t0    = chunk * ROWS;
    const int tid   = threadIdx.x;
    const int lane  = tid & (LANES - 1);
    const int rsub  = tid >> 6;            // 0..3

    __shared__ int   s_len[NNODES];
    __shared__ int   s_incl[NNODES];       // inclusive prefix of lengths
    __shared__ int   s_map[ROWS];          // (n<<8)|p, or -1 for padding
    __shared__ int   s_lenb;
    __shared__ float4 s_acc[4][LANES];

    if (tid < NNODES) s_len[tid] = lengths[b * N + tid];
    __syncthreads();
    if (tid == 0) {
        int s = 0;
        #pragma unroll 8
        for (int i = 0; i < NNODES; ++i) { s += s_len[i]; s_incl[i] = s; }
        s_lenb = s;
    }
    __syncthreads();
    const int len_b = s_lenb;

    // ---- map each of my ROWS output rows to (node, pos) or padding ---------
    if (tid < ROWS) {
        int t = t0 + tid;
        int m = -1;
        if (t < len_b) {
            // smallest n with incl[n] > t  (len[n] > 0 guaranteed)
            int lo = 0, hi = NNODES;
            while (lo < hi) {
                int mid = (lo + hi) >> 1;
                if (s_incl[mid] > t) hi = mid; else lo = mid + 1;
            }
            int n   = lo;
            int off = s_incl[n] - s_len[n];
            m = (n << 8) | (t - off);
        }
        s_map[tid] = m;
    }
    __syncthreads();

    // ---- main copy: gather source rows (or zeros), streaming writes --------
    const float4* __restrict__ mb4 = reinterpret_cast<const float4*>(mb);
    float4* __restrict__ out4 =
        reinterpret_cast<float4*>(mb_out) + ((size_t)t0 * B + b) * LANES + lane;
    const size_t ostep = (size_t)B * LANES;          // float4 elems per row

    float4 acc = make_float4(0.f, 0.f, 0.f, 0.f);
    #pragma unroll 4
    for (int r8 = 0; r8 < ROWS / 4; ++r8) {
        const int r = r8 * 4 + rsub;
        const int m = s_map[r];
        float4 v = make_float4(0.f, 0.f, 0.f, 0.f);
        if (m >= 0) {
            const int n = m >> 8;
            const int p = m & 255;
            v = mb4[((size_t)p * NB + (b * N + n)) * LANES + lane];
            acc.x += v.x; acc.y += v.y; acc.z += v.z; acc.w += v.w;
        }
        out4[(size_t)r * ostep] = v;
    }
    s_acc[rsub][lane] = acc;

    // ---- src_out: one scalar per row ---------------------------------------
    if (tid < ROWS) {
        const int t = t0 + tid;
        const int m = s_map[tid];
        float val = 1.0f;
        if (m >= 0) {
            const int n = m >> 8;
            const int p = m & 255;
            val = src[(size_t)p * NB + recover[b * N + n]];
        }
        src_out[(size_t)t * B + b] = val;
    }

    __syncthreads();

    // ---- hidden partials: cross-rsub reduce -> 4 atomics/thread ------------
    if (rsub == 0 && t0 < len_b) {
        float4 a0 = s_acc[0][lane], a1 = s_acc[1][lane];
        float4 a2 = s_acc[2][lane], a3 = s_acc[3][lane];
        float inv = 1.0f / (float)len_b;
        float* h = hidden + (size_t)b * D + lane * 4;
        atomicAdd(h + 0, (a0.x + a1.x + a2.x + a3.x) * inv);
        atomicAdd(h + 1, (a0.y + a1.y + a2.y + a3.y) * inv);
        atomicAdd(h + 2, (a0.z + a1.z + a2.z + a3.z) * inv);
        atomicAdd(h + 3, (a0.w + a1.w + a2.w + a3.w) * inv);
    }

    if (chunk == 0 && tid == 0)
        lengths_out[b] = (float)len_b;
}

extern "C" void kernel_launch(void* const* d_in, const int* in_sizes, int n_in,
                              void* d_out, int out_size)
{
    const float* src     = (const float*)d_in[0];
    const float* mb      = (const float*)d_in[1];
    const int*   lengths = (const int*)d_in[2];
    const int*   recover = (const int*)d_in[3];

    const long long NB = in_sizes[2];
    const long long L  = in_sizes[0] / NB;
    const long long D  = in_sizes[1] / in_sizes[0];
    const long long B  = (long long)out_size / (D + 1) - NB * L;
    const long long N  = NB / B;
    const long long MAX_LEN = N * L;

    float* out = (float*)d_out;
    float* src_out     = out;
    float* mb_out      = out + (size_t)MAX_LEN * B;
    float* hidden      = mb_out + (size_t)MAX_LEN * B * D;
    float* lengths_out = hidden + (size_t)B * D;

    {
        int n4 = (int)((B * D) / 4);
        zero_hidden_kernel<<<(n4 + 255) / 256, 256>>>(hidden, n4);
    }
    {
        dim3 grid((unsigned)(MAX_LEN / ROWS), (unsigned)B);
        recon_kernel<<<grid, 256>>>(src, mb, lengths, recover,
                                    src_out, mb_out, hidden, lengths_out,
                                    (int)B, (int)N, (int)D, (int)NB, (int)MAX_LEN);
    }
}